// round 7
// baseline (speedup 1.0000x reference)
#include <cuda_runtime.h>

#define DD   128
#define NN   21845          // (4^8 - 1) / 3
#define NPOS 18
#define NDEP 46

__host__ __device__ __forceinline__ int lvl_start(int l) {
    return ((1 << (2 * l)) - 1) / 3;
}

typedef unsigned long long ull;

// FFMA2 (packed f32x2), only reachable via PTX
__device__ __forceinline__ void fma2(ull& acc, ull a, ull b) {
    asm("fma.rn.f32x2 %0, %1, %2, %0;" : "+l"(acc) : "l"(a), "l"(b));
}
__device__ __forceinline__ void unpack2(ull v, float& lo, float& hi) {
    asm("mov.b64 {%0, %1}, %2;" : "=f"(lo), "=f"(hi) : "l"(v));
}
__device__ __forceinline__ float4 max4(float4 a, float4 b) {
    float4 r;
    r.x = fmaxf(a.x, b.x); r.y = fmaxf(a.y, b.y);
    r.z = fmaxf(a.z, b.z); r.w = fmaxf(a.w, b.w);
    return r;
}
// XOR swizzle: makes 32B-stride 16B smem accesses conflict-free
__device__ __forceinline__ unsigned sw16(unsigned b) {
    return b ^ ((b >> 3) & 0x10u);
}

// persistent scratch (device globals: allocation-free)
__device__ float g_xz[NN * DD];            // x from pos stage
__device__ float g_u[NN * DD];             // u outputs keyed by global child idx
__device__ int   g_pos_perm[NN];
__device__ int   g_pos_off[NPOS + 1];
__device__ int   g_pos_tg[384], g_pos_tb[384];
__device__ int   g_pos_nt;
__device__ int   g_dep_perm[NN];
__device__ int   g_dep_off[7][NDEP + 1];
__device__ int   g_dep_tg[7][320], g_dep_tb[7][320];
__device__ int   g_dep_nt[7];
__device__ unsigned g_bar_cnt;
__device__ unsigned g_bar_gen;

__device__ __forceinline__ void gridbar(int nb) {
    __syncthreads();
    if (threadIdx.x == 0) {
        __threadfence();
        unsigned gen = *(volatile unsigned*)&g_bar_gen;
        if (atomicAdd(&g_bar_cnt, 1u) == (unsigned)nb - 1u) {
            atomicExch(&g_bar_cnt, 0u);
            __threadfence();
            atomicAdd(&g_bar_gen, 1u);
        } else {
            while (*(volatile unsigned*)&g_bar_gen == gen) __nanosleep(64);
        }
        __threadfence();
    }
    __syncthreads();
}

// ---------------------------------------------------------------------------
// Grouping: block 0 = pos, blocks 1..7 = dep level b-1
// ---------------------------------------------------------------------------
__global__ void group_kernel(const int* __restrict__ pos_ids,
                             const int* __restrict__ dep_ids) {
    __shared__ int cnt[NDEP];
    __shared__ int off[NDEP + 1];
    int t = threadIdx.x, lane = t & 31;
    const int* ids; int n, ng, base, BM;
    int *perm, *goff, *tg, *tb, *nt_out;
    if (blockIdx.x == 0) {
        ids = pos_ids; n = NN; ng = NPOS; base = 0; BM = 64;
        perm = g_pos_perm; goff = g_pos_off;
        tg = g_pos_tg; tb = g_pos_tb; nt_out = &g_pos_nt;
    } else {
        int l = blockIdx.x - 1;
        base = lvl_start(l + 1); n = 1 << (2 * (l + 1)); ng = NDEP;
        BM = (l >= 5) ? 64 : 16;
        ids = dep_ids + base; perm = g_dep_perm + base; goff = g_dep_off[l];
        tg = g_dep_tg[l]; tb = g_dep_tb[l]; nt_out = &g_dep_nt[l];
    }
    if (t < ng) cnt[t] = 0;
    __syncthreads();
    for (int i0 = 0; i0 < n; i0 += blockDim.x) {
        int i = i0 + t; bool v = (i < n);
        unsigned act = __ballot_sync(0xffffffffu, v);
        if (v) {
            int id = ids[i];
            unsigned m = __match_any_sync(act, id);
            if (lane == __ffs(m) - 1) atomicAdd(&cnt[id], __popc(m));
        }
    }
    __syncthreads();
    if (t == 0) {
        int s = 0;
        for (int j = 0; j < ng; ++j) { off[j] = s; s += cnt[j]; }
        off[ng] = s;
        int nt = 0;
        for (int j = 0; j < ng; ++j) {
            int c = off[j + 1] - off[j];
            for (int k = 0; k < c; k += BM) { tg[nt] = j; tb[nt] = off[j] + k; ++nt; }
        }
        *nt_out = nt;
        for (int j = 0; j <= ng; ++j) goff[j] = off[j];
    }
    __syncthreads();
    if (t < ng) cnt[t] = off[t];
    __syncthreads();
    for (int i0 = 0; i0 < n; i0 += blockDim.x) {
        int i = i0 + t; bool v = (i < n);
        unsigned act = __ballot_sync(0xffffffffu, v);
        if (v) {
            int id = ids[i];
            unsigned m = __match_any_sync(act, id);
            int leader = __ffs(m) - 1;
            int prior = __popc(m & ((1u << lane) - 1u));
            int bp = 0;
            if (lane == leader) bp = atomicAdd(&cnt[id], __popc(m));
            bp = __shfl_sync(act, bp, leader);
            perm[bp + prior] = base + i;
        }
    }
}

// ---------------------------------------------------------------------------
// Big grouped GEMM: BM=64 x BN=128, K=128, 256 threads, 2 CTAs/SM.
// Packed-k FFMA2: acc[row][col] pairs over (k, k+1); no ALU movs.
// W smem is pair-major interleaved: chunk(kp, c0=4cb) = 2 float4s
//   {w_k,c0, w_k+1,c0, w_k,c1, w_k+1,c1}, {c2,c3...}, XOR-swizzled.
// mode 0: A=emb[node] -> g_xz ; mode 1: A=g_xz -> g_u ; mode 2: A=maxgather -> g_u
// ---------------------------------------------------------------------------
#define SMEM_BIG (65536 + 64 * 128 * 4)

__global__ __launch_bounds__(256, 2)
void gemm_big(int mode, const float* __restrict__ Wsrc,
              const float* __restrict__ bias, const float* __restrict__ srcA,
              const int* __restrict__ nt_p, const int* __restrict__ tg,
              const int* __restrict__ tb, const int* __restrict__ off,
              const int* __restrict__ perm, int cs_row, int cs_child)
{
    int tile = blockIdx.x;
    if (tile >= *nt_p) return;
    extern __shared__ __align__(16) char smc[];
    char*  sWb = smc;                        // 64KB pair-major W
    float* sA  = (float*)(smc + 65536);      // 64x128 row-major A
    __shared__ int sNode[64];
    int t = threadIdx.x;
    int j = tg[tile], b0 = tb[tile];
    int mc = off[j + 1] - b0; if (mc > 64) mc = 64;
    if (t < 64) sNode[t] = perm[b0 + min(t, mc - 1)];
    // --- W staging: pair-major interleave ---
    const float4* W4 = (const float4*)(Wsrc + (size_t)j * 16384);
#pragma unroll
    for (int i = 0; i < 8; ++i) {
        int idx = t + 256 * i;               // 0..2047
        int kp = idx >> 5, cb = idx & 31;
        float4 r0 = W4[64 * kp + cb];        // row 2kp,   cols 4cb..
        float4 r1 = W4[64 * kp + 32 + cb];   // row 2kp+1
        float4 s0 = make_float4(r0.x, r1.x, r0.y, r1.y);
        float4 s1 = make_float4(r0.z, r1.z, r0.w, r1.w);
        unsigned b = (unsigned)(kp * 1024 + cb * 32);
        *(float4*)(sWb + sw16(b))      = s0;
        *(float4*)(sWb + sw16(b + 16)) = s1;
    }
    __syncthreads();
    // --- A staging ---
    if (mode < 2) {
        const float4* A4 = (const float4*)srcA;
#pragma unroll
        for (int i = 0; i < 8; ++i) {
            int idx = t + 256 * i; int r = idx >> 5, c = idx & 31;
            ((float4*)(sA + r * 128))[c] = A4[(size_t)sNode[r] * 32 + c];
        }
    } else {
        const float4* X4 = (const float4*)g_xz;
        const float4* U4 = (const float4*)g_u;
#pragma unroll
        for (int i = 0; i < 8; ++i) {
            int idx = t + 256 * i; int r = idx >> 5, c = idx & 31;
            int node = sNode[r];
            int ch = cs_child + 4 * (node - cs_row);
            float4 v = X4[(size_t)node * 32 + c];
            v = max4(v, U4[(size_t)(ch + 0) * 32 + c]);
            v = max4(v, U4[(size_t)(ch + 1) * 32 + c]);
            v = max4(v, U4[(size_t)(ch + 2) * 32 + c]);
            v = max4(v, U4[(size_t)(ch + 3) * 32 + c]);
            ((float4*)(sA + r * 128))[c] = v;
        }
    }
    __syncthreads();
    int tx = t & 31, ty = t >> 5;
    ull acc[8][4];
#pragma unroll
    for (int i = 0; i < 8; ++i)
#pragma unroll
        for (int q = 0; q < 4; ++q) acc[i][q] = 0ull;
#pragma unroll 2
    for (int k4 = 0; k4 < 32; ++k4) {
        // W chunks for kpairs 2k4 and 2k4+1, cols 4tx..4tx+3
        unsigned wb0 = (unsigned)((2 * k4) * 1024 + tx * 32);
        unsigned wb1 = wb0 + 1024;
        ulonglong2 w0a = *(const ulonglong2*)(sWb + sw16(wb0));
        ulonglong2 w0b = *(const ulonglong2*)(sWb + sw16(wb0 + 16));
        ulonglong2 w1a = *(const ulonglong2*)(sWb + sw16(wb1));
        ulonglong2 w1b = *(const ulonglong2*)(sWb + sw16(wb1 + 16));
#pragma unroll
        for (int i = 0; i < 8; ++i) {
            ulonglong2 aa = *(const ulonglong2*)&sA[(ty + 8 * i) * 128 + 4 * k4];
            fma2(acc[i][0], aa.x, w0a.x);
            fma2(acc[i][1], aa.x, w0a.y);
            fma2(acc[i][2], aa.x, w0b.x);
            fma2(acc[i][3], aa.x, w0b.y);
            fma2(acc[i][0], aa.y, w1a.x);
            fma2(acc[i][1], aa.y, w1a.y);
            fma2(acc[i][2], aa.y, w1b.x);
            fma2(acc[i][3], aa.y, w1b.y);
        }
    }
    float4 bv = *(const float4*)&bias[j * 128 + 4 * tx];
    float* dst = (mode == 0) ? g_xz : g_u;
#pragma unroll
    for (int i = 0; i < 8; ++i) {
        int node = sNode[ty + 8 * i];
        float lo, hi; float4 o;
        unpack2(acc[i][0], lo, hi); o.x = fmaxf(lo + hi + bv.x, 0.f);
        unpack2(acc[i][1], lo, hi); o.y = fmaxf(lo + hi + bv.y, 0.f);
        unpack2(acc[i][2], lo, hi); o.z = fmaxf(lo + hi + bv.z, 0.f);
        unpack2(acc[i][3], lo, hi); o.w = fmaxf(lo + hi + bv.w, 0.f);
        *(float4*)&dst[(size_t)node * 128 + 4 * tx] = o;
    }
}

// ---------------------------------------------------------------------------
// Narrow persistent kernel: dep levels 4..0 (packed-k FFMA2), root finalize.
// item = (16-row tile) x (32-col slice); 256 thr: 16 rows x 16 thr x 2 cols.
// ---------------------------------------------------------------------------
__global__ __launch_bounds__(256, 2)
void narrow_all(const float* __restrict__ Wsrc, const float* __restrict__ bias,
                float* __restrict__ out)
{
    __shared__ __align__(16) char sWn[64 * 256];    // 16KB pair-major W slice
    __shared__ __align__(16) float sA2[16 * 128];
    __shared__ int sN[16];
    int t = threadIdx.x;
    int nb = gridDim.x;
    for (int l = 4; l >= 0; --l) {
        int cs_row = lvl_start(l + 1);
        int cs_child = lvl_start(l + 2);
        int nt = g_dep_nt[l];
        int items = nt * 4;
        const int* tg = g_dep_tg[l];
        const int* tb = g_dep_tb[l];
        const int* off = g_dep_off[l];
        for (int item = blockIdx.x; item < items; item += nb) {
            __syncthreads();
            int tile = item >> 2, slice = item & 3, c0 = slice * 32;
            int j = tg[tile], b0 = tb[tile];
            int mc = off[j + 1] - b0; if (mc > 16) mc = 16;
            if (t < 16) sN[t] = g_dep_perm[cs_row + b0 + min(t, mc - 1)];
            // W slice staging: pair-major
            const float* Wj = Wsrc + (size_t)j * 16384;
#pragma unroll
            for (int i = 0; i < 2; ++i) {
                int idx = t + 256 * i;        // 0..511
                int kp = idx >> 3, cb = idx & 7;
                float4 r0 = *(const float4*)&Wj[(2 * kp) * 128 + c0 + 4 * cb];
                float4 r1 = *(const float4*)&Wj[(2 * kp + 1) * 128 + c0 + 4 * cb];
                float4 s0 = make_float4(r0.x, r1.x, r0.y, r1.y);
                float4 s1 = make_float4(r0.z, r1.z, r0.w, r1.w);
                unsigned b = (unsigned)(kp * 256 + cb * 32);
                *(float4*)(sWn + sw16(b))      = s0;
                *(float4*)(sWn + sw16(b + 16)) = s1;
            }
            __syncthreads();
            const float4* X4 = (const float4*)g_xz;
            const float4* U4 = (const float4*)g_u;
#pragma unroll
            for (int i = 0; i < 2; ++i) {
                int idx = t + 256 * i; int r = idx >> 5, c = idx & 31;
                int node = sN[r];
                int ch = cs_child + 4 * (node - cs_row);
                float4 v = X4[(size_t)node * 32 + c];
                v = max4(v, U4[(size_t)(ch + 0) * 32 + c]);
                v = max4(v, U4[(size_t)(ch + 1) * 32 + c]);
                v = max4(v, U4[(size_t)(ch + 2) * 32 + c]);
                v = max4(v, U4[(size_t)(ch + 3) * 32 + c]);
                ((float4*)(sA2 + r * 128))[c] = v;
            }
            __syncthreads();
            int r = t >> 4, x16 = t & 15;
            ull accA = 0ull, accB = 0ull;
#pragma unroll 4
            for (int kp = 0; kp < 64; ++kp) {
                ull a = *(const ull*)&sA2[r * 128 + 2 * kp];
                ulonglong2 w = *(const ulonglong2*)(sWn + sw16((unsigned)(kp * 256 + x16 * 16)));
                fma2(accA, a, w.x);
                fma2(accB, a, w.y);
            }
            int node = sN[r];
            int col = c0 + 2 * x16;
            float2 bv = *(const float2*)&bias[j * 128 + col];
            float lo, hi; float2 o;
            unpack2(accA, lo, hi); o.x = fmaxf(lo + hi + bv.x, 0.f);
            unpack2(accB, lo, hi); o.y = fmaxf(lo + hi + bv.y, 0.f);
            *(float2*)&g_u[(size_t)node * 128 + col] = o;
        }
        gridbar(nb);
    }
    // root finalize: out = max(x[0], u of nodes 1..4)
    if (blockIdx.x == 0 && t < 32) {
        const float4* X4 = (const float4*)g_xz;
        const float4* U4 = (const float4*)g_u;
        float4 v = X4[t];
        v = max4(v, U4[1 * 32 + t]);
        v = max4(v, U4[2 * 32 + t]);
        v = max4(v, U4[3 * 32 + t]);
        v = max4(v, U4[4 * 32 + t]);
        ((float4*)out)[t] = v;
    }
}

// ---------------------------------------------------------------------------
extern "C" void kernel_launch(void* const* d_in, const int* in_sizes, int n_in,
                              void* d_out, int out_size) {
    const float* emb     = (const float*)d_in[0];
    const int*   pos_ids = (const int*)d_in[1];
    const int*   dep_ids = (const int*)d_in[2];
    const float* pos_W   = (const float*)d_in[3];
    const float* pos_b   = (const float*)d_in[4];
    const float* dep_W   = (const float*)d_in[5];
    const float* dep_b   = (const float*)d_in[6];

    cudaFuncSetAttribute(gemm_big, cudaFuncAttributeMaxDynamicSharedMemorySize,
                         SMEM_BIG);

    int *d_pos_nt, *d_pos_tg, *d_pos_tb, *d_pos_off, *d_pos_perm;
    int *d_dep_nt, *d_dep_tg, *d_dep_tb, *d_dep_off, *d_dep_perm;
    cudaGetSymbolAddress((void**)&d_pos_nt,   g_pos_nt);
    cudaGetSymbolAddress((void**)&d_pos_tg,   g_pos_tg);
    cudaGetSymbolAddress((void**)&d_pos_tb,   g_pos_tb);
    cudaGetSymbolAddress((void**)&d_pos_off,  g_pos_off);
    cudaGetSymbolAddress((void**)&d_pos_perm, g_pos_perm);
    cudaGetSymbolAddress((void**)&d_dep_nt,   g_dep_nt);
    cudaGetSymbolAddress((void**)&d_dep_tg,   g_dep_tg);
    cudaGetSymbolAddress((void**)&d_dep_tb,   g_dep_tb);
    cudaGetSymbolAddress((void**)&d_dep_off,  g_dep_off);
    cudaGetSymbolAddress((void**)&d_dep_perm, g_dep_perm);
    float* d_xz;
    cudaGetSymbolAddress((void**)&d_xz, g_xz);

    group_kernel<<<8, 1024>>>(pos_ids, dep_ids);

    // pos: all NN nodes -> g_xz
    gemm_big<<<360, 256, SMEM_BIG>>>(0, pos_W, pos_b, emb,
        d_pos_nt, d_pos_tg, d_pos_tb, d_pos_off, d_pos_perm, 0, 0);

    // dep level 6: rows = level-7 nodes (z = x), u -> g_u
    gemm_big<<<302, 256, SMEM_BIG>>>(1, dep_W, dep_b, d_xz,
        d_dep_nt + 6, d_dep_tg + 6 * 320, d_dep_tb + 6 * 320,
        d_dep_off + 6 * (NDEP + 1), d_dep_perm + lvl_start(7),
        lvl_start(7), 0);

    // dep level 5: rows = level-6 nodes, fused max-gather, u -> g_u
    gemm_big<<<110, 256, SMEM_BIG>>>(2, dep_W, dep_b, d_xz,
        d_dep_nt + 5, d_dep_tg + 5 * 320, d_dep_tb + 5 * 320,
        d_dep_off + 5 * (NDEP + 1), d_dep_perm + lvl_start(6),
        lvl_start(6), lvl_start(7));

    // levels 4..0 + root finalize in one persistent kernel
    int dev = 0, nsm = 0, occ = 0;
    cudaGetDevice(&dev);
    cudaDeviceGetAttribute(&nsm, cudaDevAttrMultiProcessorCount, dev);
    cudaOccupancyMaxActiveBlocksPerMultiprocessor(&occ, narrow_all, 256, 0);
    if (occ < 1) occ = 1;
    int grid = nsm * (occ < 2 ? occ : 2);
    narrow_all<<<grid, 256>>>(dep_W, dep_b, (float*)d_out);
}